// round 1
// baseline (speedup 1.0000x reference)
#include <cuda_runtime.h>

// mLSTM cell, B=32768, H=512, fp32 end-to-end.
// Kernel 1: m = x@W_m + h@U_m + b_m ; x_tilde = x * m  -> scratch
// Kernel 2: 4 gate pre-activations (8 GEMMs, shared A tiles) + fused cell update -> h_t

#define BDIM 32768
#define HDIM 512

// 64 MB scratch for x_tilde (allocation-free: __device__ global)
__device__ float g_xtilde[(size_t)BDIM * HDIM];

// ---- packed f32x2 helpers (FFMA2: 2 fp32 FMAs per instruction) ----
__device__ __forceinline__ unsigned long long pack2(float v) {
    unsigned long long r;
    asm("mov.b64 %0, {%1, %1};" : "=l"(r) : "f"(v));
    return r;
}
__device__ __forceinline__ void fma2(unsigned long long& d,
                                     unsigned long long a,
                                     unsigned long long b) {
    asm("fma.rn.f32x2 %0, %1, %2, %0;" : "+l"(d) : "l"(a), "l"(b));
}
__device__ __forceinline__ float2 unpack2(unsigned long long v) {
    float2 f;
    asm("mov.b64 {%0, %1}, %2;" : "=f"(f.x), "=f"(f.y) : "l"(v));
    return f;
}

__device__ __forceinline__ float sigmoidf_fast(float z) {
    return 1.0f / (1.0f + __expf(-z));
}

// ============================================================================
// Kernel 1: m-gate GEMM + x_tilde epilogue
// Tile: 64x64 per CTA, 256 threads, each thread 4x4 outputs, K-chunk = 16
// ============================================================================
__global__ __launch_bounds__(256) void k_mgate(
    const float* __restrict__ x, const float* __restrict__ h,
    const float* __restrict__ Wm, const float* __restrict__ Um,
    const float* __restrict__ bm)
{
    __shared__ float As_x[16][64];
    __shared__ float As_h[16][64];
    __shared__ float Bs_w[16][64];
    __shared__ float Bs_u[16][64];

    const int n0 = blockIdx.x * 64;
    const int m0 = blockIdx.y * 64;
    const int tid = threadIdx.x;
    const int tm = tid >> 4;          // 0..15
    const int tn = tid & 15;          // 0..15

    // global->smem load mapping
    const int lm = tid >> 2;          // 0..63 (A rows)
    const int lk = (tid & 3) * 4;     // 0,4,8,12 (A cols, float4)
    const int bk = tid >> 4;          // 0..15 (B rows)
    const int bn = (tid & 15) * 4;    // B cols, float4

    unsigned long long acc[4][2];
#pragma unroll
    for (int i = 0; i < 4; i++)
#pragma unroll
        for (int j = 0; j < 2; j++) acc[i][j] = 0ull;

    const size_t arow = (size_t)(m0 + lm) * HDIM;

    for (int k0 = 0; k0 < HDIM; k0 += 16) {
        float4 gx = *(const float4*)&x[arow + k0 + lk];
        float4 gh = *(const float4*)&h[arow + k0 + lk];
        float4 gw = *(const float4*)&Wm[(size_t)(k0 + bk) * HDIM + n0 + bn];
        float4 gu = *(const float4*)&Um[(size_t)(k0 + bk) * HDIM + n0 + bn];
        __syncthreads();
        As_x[lk + 0][lm] = gx.x; As_x[lk + 1][lm] = gx.y;
        As_x[lk + 2][lm] = gx.z; As_x[lk + 3][lm] = gx.w;
        As_h[lk + 0][lm] = gh.x; As_h[lk + 1][lm] = gh.y;
        As_h[lk + 2][lm] = gh.z; As_h[lk + 3][lm] = gh.w;
        *(float4*)&Bs_w[bk][bn] = gw;
        *(float4*)&Bs_u[bk][bn] = gu;
        __syncthreads();

#pragma unroll
        for (int kk = 0; kk < 16; kk++) {
            float4 ax = *(const float4*)&As_x[kk][tm * 4];
            float4 ah = *(const float4*)&As_h[kk][tm * 4];
            ulonglong2 bw = *(const ulonglong2*)&Bs_w[kk][tn * 4];
            ulonglong2 bu = *(const ulonglong2*)&Bs_u[kk][tn * 4];
            unsigned long long apx[4] = {pack2(ax.x), pack2(ax.y), pack2(ax.z), pack2(ax.w)};
            unsigned long long aph[4] = {pack2(ah.x), pack2(ah.y), pack2(ah.z), pack2(ah.w)};
#pragma unroll
            for (int i = 0; i < 4; i++) {
                fma2(acc[i][0], apx[i], bw.x);
                fma2(acc[i][1], apx[i], bw.y);
                fma2(acc[i][0], aph[i], bu.x);
                fma2(acc[i][1], aph[i], bu.y);
            }
        }
    }

    // epilogue: x_tilde = x * (m + b_m)
#pragma unroll
    for (int i = 0; i < 4; i++) {
        const int m = m0 + tm * 4 + i;
        const size_t rbase = (size_t)m * HDIM;
#pragma unroll
        for (int j2 = 0; j2 < 2; j2++) {
            float2 v = unpack2(acc[i][j2]);
            const int n = n0 + tn * 4 + j2 * 2;
            float2 xv = *(const float2*)&x[rbase + n];
            float2 r;
            r.x = xv.x * (v.x + bm[n]);
            r.y = xv.y * (v.y + bm[n + 1]);
            *(float2*)&g_xtilde[rbase + n] = r;
        }
    }
}

// ============================================================================
// Kernel 2: 4 gates (8 GEMMs fused) + cell update -> h_t
// Gate order: 0=i (A: x_tilde), 1=f, 2=o, 3=c (A: x); all use h for U-part
// ============================================================================
__global__ __launch_bounds__(256) void k_gates(
    const float* __restrict__ x, const float* __restrict__ h,
    const float* __restrict__ c_prev,
    const float* __restrict__ Wi, const float* __restrict__ Ui,
    const float* __restrict__ Wf, const float* __restrict__ Uf,
    const float* __restrict__ Wo, const float* __restrict__ Uo,
    const float* __restrict__ Wc, const float* __restrict__ Uc,
    const float* __restrict__ bi, const float* __restrict__ bf,
    const float* __restrict__ bo, const float* __restrict__ bc,
    float* __restrict__ out)
{
    __shared__ float As_x[16][64];
    __shared__ float As_t[16][64];
    __shared__ float As_h[16][64];
    __shared__ float Bs[8][16][64];   // Wi,Ui,Wf,Uf,Wo,Uo,Wc,Uc

    const int n0 = blockIdx.x * 64;
    const int m0 = blockIdx.y * 64;
    const int tid = threadIdx.x;
    const int tm = tid >> 4;
    const int tn = tid & 15;

    const int lm = tid >> 2;
    const int lk = (tid & 3) * 4;
    const int bk = tid >> 4;
    const int bn = (tid & 15) * 4;

    const float* Ws[8] = {Wi, Ui, Wf, Uf, Wo, Uo, Wc, Uc};

    unsigned long long acc[4][4][2];  // [gate][i][j2]
#pragma unroll
    for (int g = 0; g < 4; g++)
#pragma unroll
        for (int i = 0; i < 4; i++)
#pragma unroll
            for (int j = 0; j < 2; j++) acc[g][i][j] = 0ull;

    const size_t arow = (size_t)(m0 + lm) * HDIM;

    for (int k0 = 0; k0 < HDIM; k0 += 16) {
        float4 gx = *(const float4*)&x[arow + k0 + lk];
        float4 gt = *(const float4*)&g_xtilde[arow + k0 + lk];
        float4 gh = *(const float4*)&h[arow + k0 + lk];
        float4 gb[8];
#pragma unroll
        for (int w = 0; w < 8; w++)
            gb[w] = *(const float4*)&Ws[w][(size_t)(k0 + bk) * HDIM + n0 + bn];

        __syncthreads();
        As_x[lk + 0][lm] = gx.x; As_x[lk + 1][lm] = gx.y;
        As_x[lk + 2][lm] = gx.z; As_x[lk + 3][lm] = gx.w;
        As_t[lk + 0][lm] = gt.x; As_t[lk + 1][lm] = gt.y;
        As_t[lk + 2][lm] = gt.z; As_t[lk + 3][lm] = gt.w;
        As_h[lk + 0][lm] = gh.x; As_h[lk + 1][lm] = gh.y;
        As_h[lk + 2][lm] = gh.z; As_h[lk + 3][lm] = gh.w;
#pragma unroll
        for (int w = 0; w < 8; w++)
            *(float4*)&Bs[w][bk][bn] = gb[w];
        __syncthreads();

#pragma unroll
        for (int kk = 0; kk < 16; kk++) {
            float4 ax = *(const float4*)&As_x[kk][tm * 4];
            float4 at = *(const float4*)&As_t[kk][tm * 4];
            float4 ah = *(const float4*)&As_h[kk][tm * 4];
            unsigned long long apx[4] = {pack2(ax.x), pack2(ax.y), pack2(ax.z), pack2(ax.w)};
            unsigned long long apt[4] = {pack2(at.x), pack2(at.y), pack2(at.z), pack2(at.w)};
            unsigned long long aph[4] = {pack2(ah.x), pack2(ah.y), pack2(ah.z), pack2(ah.w)};
#pragma unroll
            for (int g = 0; g < 4; g++) {
                ulonglong2 bw = *(const ulonglong2*)&Bs[2 * g][kk][tn * 4];
                ulonglong2 bu = *(const ulonglong2*)&Bs[2 * g + 1][kk][tn * 4];
#pragma unroll
                for (int i = 0; i < 4; i++) {
                    unsigned long long a0 = (g == 0) ? apt[i] : apx[i];
                    fma2(acc[g][i][0], a0, bw.x);
                    fma2(acc[g][i][1], a0, bw.y);
                    fma2(acc[g][i][0], aph[i], bu.x);
                    fma2(acc[g][i][1], aph[i], bu.y);
                }
            }
        }
    }

    // fused cell-update epilogue
#pragma unroll
    for (int i = 0; i < 4; i++) {
        const int m = m0 + tm * 4 + i;
        const size_t rbase = (size_t)m * HDIM;
#pragma unroll
        for (int j2 = 0; j2 < 2; j2++) {
            const int n = n0 + tn * 4 + j2 * 2;
            float2 vi = unpack2(acc[0][i][j2]);
            float2 vf = unpack2(acc[1][i][j2]);
            float2 vo = unpack2(acc[2][i][j2]);
            float2 vc = unpack2(acc[3][i][j2]);
            float2 cp = *(const float2*)&c_prev[rbase + n];
            float2 r;
            {
                float ig = sigmoidf_fast(vi.x + bi[n]);
                float fg = sigmoidf_fast(vf.x + bf[n]);
                float og = sigmoidf_fast(vo.x + bo[n]);
                float ct = tanhf(vc.x + bc[n]);
                float cc = fg * cp.x + ig * ct;
                r.x = og * tanhf(cc);
            }
            {
                float ig = sigmoidf_fast(vi.y + bi[n + 1]);
                float fg = sigmoidf_fast(vf.y + bf[n + 1]);
                float og = sigmoidf_fast(vo.y + bo[n + 1]);
                float ct = tanhf(vc.y + bc[n + 1]);
                float cc = fg * cp.y + ig * ct;
                r.y = og * tanhf(cc);
            }
            *(float2*)&out[rbase + n] = r;
        }
    }
}

// ============================================================================
extern "C" void kernel_launch(void* const* d_in, const int* in_sizes, int n_in,
                              void* d_out, int out_size) {
    const float* x  = (const float*)d_in[0];
    const float* h  = (const float*)d_in[1];
    const float* c  = (const float*)d_in[2];
    const float* Wm = (const float*)d_in[3];
    const float* Um = (const float*)d_in[4];
    const float* Wi = (const float*)d_in[5];
    const float* Ui = (const float*)d_in[6];
    const float* Wf = (const float*)d_in[7];
    const float* Uf = (const float*)d_in[8];
    const float* Wo = (const float*)d_in[9];
    const float* Uo = (const float*)d_in[10];
    const float* Wc = (const float*)d_in[11];
    const float* Uc = (const float*)d_in[12];
    const float* bm = (const float*)d_in[13];
    const float* bi = (const float*)d_in[14];
    const float* bf = (const float*)d_in[15];
    const float* bo = (const float*)d_in[16];
    const float* bc = (const float*)d_in[17];
    float* out = (float*)d_out;

    dim3 grid(HDIM / 64, BDIM / 64);
    dim3 block(256);
    k_mgate<<<grid, block>>>(x, h, Wm, Um, bm);
    k_gates<<<grid, block>>>(x, h, c, Wi, Ui, Wf, Uf, Wo, Uo, Wc, Uc,
                             bi, bf, bo, bc, out);
}